// round 1
// baseline (speedup 1.0000x reference)
#include <cuda_runtime.h>

#define NB 64
#define NP 1024
#define CF 16
#define KK 16
#define BN_EPS 1e-5f

// ---------------- static scratch (no allocations allowed) ----------------
__device__ float g_C [NB*NP*64];   // per-point center projection (BN-folded, pre-relu)
__device__ float g_Y [NB*NP*64];   // per-point neighbor projection (scaled)
__device__ float g_SC[NB*NP*64];   // shortcut (BN-folded, mask-zeroed)
__device__ int   g_idx[NB*NP*KK];  // knn indices
__device__ int   g_valid[NB];
__device__ float g_W1f[64*64];     // W1 row-scaled by s1 (row-major [o][c])
__device__ float g_W2f[64*64];
__device__ float g_s0[64], g_t0[64], g_t1[64], g_t2[64], g_ss[64], g_ts[64];

// ---------------- fold BN into weights / biases ----------------
__global__ void fold_kernel(const float* __restrict__ W1, const float* __restrict__ W2,
    const float* g0,const float* b0,const float* m0,const float* v0,
    const float* g1,const float* b1,const float* m1,const float* v1,
    const float* g2,const float* b2,const float* m2,const float* v2,
    const float* gs,const float* bs,const float* ms,const float* vs)
{
    int t = blockIdx.x*blockDim.x + threadIdx.x;
    if (t < 64){
        float s0 = g0[t]*rsqrtf(v0[t]+BN_EPS); g_s0[t]=s0; g_t0[t]=b0[t]-m0[t]*s0;
        float s1 = g1[t]*rsqrtf(v1[t]+BN_EPS); g_t1[t]=b1[t]-m1[t]*s1;
        float s2 = g2[t]*rsqrtf(v2[t]+BN_EPS); g_t2[t]=b2[t]-m2[t]*s2;
        float ss = gs[t]*rsqrtf(vs[t]+BN_EPS); g_ss[t]=ss; g_ts[t]=bs[t]-ms[t]*ss;
    }
    if (t < 4096){
        int oo = t >> 6;
        g_W1f[t] = W1[t]*(g1[oo]*rsqrtf(v1[oo]+BN_EPS));
        g_W2f[t] = W2[t]*(g2[oo]*rsqrtf(v2[oo]+BN_EPS));
    }
}

// ---------------- per-point projections: C, Y, shortcut ----------------
// layer0: h@W0^T = x_p @ (W0a+W0b)^T - x_q @ W0b^T  (W0 is [64,32], a=cols 0..15, b=16..31)
__global__ void prep_kernel(const float* __restrict__ feats,
                            const unsigned char* __restrict__ mask,
                            const float* __restrict__ W0,
                            const float* __restrict__ Ws)
{
    const int lp = threadIdx.x >> 6;     // 4 points per 256-thread block
    const int o  = threadIdx.x & 63;
    const int pt = blockIdx.x*4 + lp;    // 0 .. NB*NP-1
    __shared__ float sx[4][CF];
    if (o < CF) sx[lp][o] = feats[pt*(2+CF) + 2 + o];
    __syncthreads();
    float a = 0.f, yb = 0.f, sc = 0.f;
#pragma unroll
    for (int c = 0; c < CF; c++){
        float x  = sx[lp][c];
        float wa = W0[o*32 + c];
        float wb = W0[o*32 + 16 + c];
        a  = fmaf(x, wa + wb, a);
        yb = fmaf(x, wb, yb);
        sc = fmaf(x, Ws[o*16 + c], sc);
    }
    float s0 = g_s0[o];
    g_C[pt*64 + o] = fmaf(a, s0, g_t0[o]);
    g_Y[pt*64 + o] = yb*s0;
    float scv = fmaf(sc, g_ss[o], g_ts[o]);
    if (mask[pt]) scv = 0.f;
    g_SC[pt*64 + o] = scv;
}

// ---------------- KNN: top-16 by squared distance, excluding self ----------------
__global__ void knn_kernel(const float* __restrict__ feats,
                           const unsigned char* __restrict__ mask)
{
    const int n = blockIdx.x >> 2;                       // 4 blocks per batch
    const int p = ((blockIdx.x & 3) << 8) + threadIdx.x; // this thread's point
    __shared__ float px[NP], py[NP], rr[NP];
    __shared__ int scnt;
    if (threadIdx.x == 0) scnt = 0;
    __syncthreads();
    int mcnt = 0;
    for (int i = threadIdx.x; i < NP; i += 256){
        float x = feats[(n*NP + i)*(2+CF) + 0];
        float y = feats[(n*NP + i)*(2+CF) + 1];
        px[i] = x; py[i] = y; rr[i] = x*x + y*y;
        if (mask[n*NP + i]) mcnt++;
    }
    if (mcnt) atomicAdd(&scnt, mcnt);
    __syncthreads();
    if (threadIdx.x == 0 && (blockIdx.x & 3) == 0) g_valid[n] = NP - scnt;

    const float xp = px[p], yp = py[p], rp = rr[p];
    const float nx = -2.f*xp, ny = -2.f*yp;
    float bd[KK]; int bi[KK];
#pragma unroll
    for (int j = 0; j < KK; j++){ bd[j] = 3.4e38f; bi[j] = 0; }
    float worst = 3.4e38f; int ws = 0;
    for (int q = 0; q < NP; q++){
        float d = fmaf(nx, px[q], fmaf(ny, py[q], rp + rr[q]));
        if (d < worst && q != p){
#pragma unroll
            for (int j = 0; j < KK; j++) if (j == ws){ bd[j] = d; bi[j] = q; }
            worst = -1.f;
#pragma unroll
            for (int j = 0; j < KK; j++) if (bd[j] > worst){ worst = bd[j]; ws = j; }
        }
    }
#pragma unroll
    for (int j = 0; j < KK; j++) g_idx[(n*NP + p)*KK + j] = bi[j];
}

// ---------------- main edge kernel: layers 1,2 + aggregate + shortcut ----------------
// thread = (point-in-block, output channel o). Weight rows live in registers;
// activation vectors are broadcast out of SMEM via LDS.128.
__global__ void __launch_bounds__(256, 1)
edge_kernel(float* __restrict__ out)
{
    const int lp = threadIdx.x >> 6;
    const int o  = threadIdx.x & 63;
    const int pt = blockIdx.x*4 + lp;
    const int n  = pt >> 10;
    const int p  = pt & 1023;

    __shared__ float sv[4][64];
    __shared__ float su[4][64];

    float w1r[64], w2r[64];
#pragma unroll
    for (int i = 0; i < 16; i++){
        float4 a = *(const float4*)(g_W1f + o*64 + i*4);
        w1r[4*i]=a.x; w1r[4*i+1]=a.y; w1r[4*i+2]=a.z; w1r[4*i+3]=a.w;
        float4 b = *(const float4*)(g_W2f + o*64 + i*4);
        w2r[4*i]=b.x; w2r[4*i+1]=b.y; w2r[4*i+2]=b.z; w2r[4*i+3]=b.w;
    }
    const float t1o = g_t1[o], t2o = g_t2[o];
    const float c0  = g_C[pt*64 + o];
    const int valid = g_valid[n];
    const float* __restrict__ Yn = g_Y + (size_t)n*NP*64;
    const int*   __restrict__ ip = g_idx + pt*KK;

    float acc = 0.f, dcnt = 0.f;
    int   q  = ip[0];
    float yv = Yn[q*64 + o];

#pragma unroll 1
    for (int k = 0; k < KK; k++){
        const float yc = yv;
        const int   qc = q;
        if (k < KK-1){ q = ip[k+1]; yv = Yn[q*64 + o]; }  // software pipeline the gather

        sv[lp][o] = fmaxf(c0 - yc, 0.f);                  // layer0 output (relu(C_p - Y_q))
        __syncthreads();

        float a0=0.f,a1=0.f,a2=0.f,a3=0.f;
        const float4* vp = (const float4*)sv[lp];
#pragma unroll
        for (int i = 0; i < 16; i++){
            float4 v4 = vp[i];
            a0 = fmaf(w1r[4*i+0], v4.x, a0);
            a1 = fmaf(w1r[4*i+1], v4.y, a1);
            a2 = fmaf(w1r[4*i+2], v4.z, a2);
            a3 = fmaf(w1r[4*i+3], v4.w, a3);
        }
        su[lp][o] = fmaxf((a0+a1)+(a2+a3) + t1o, 0.f);    // layer1
        __syncthreads();

        a0=0.f;a1=0.f;a2=0.f;a3=0.f;
        const float4* up = (const float4*)su[lp];
#pragma unroll
        for (int i = 0; i < 16; i++){
            float4 v4 = up[i];
            a0 = fmaf(w2r[4*i+0], v4.x, a0);
            a1 = fmaf(w2r[4*i+1], v4.y, a1);
            a2 = fmaf(w2r[4*i+2], v4.z, a2);
            a3 = fmaf(w2r[4*i+3], v4.w, a3);
        }
        float w = fmaxf((a0+a1)+(a2+a3) + t2o, 0.f);      // layer2
        if (qc < valid){ acc += w; dcnt += 1.f; }         // mask_K zeroing + denom count
    }

    float denom = fmaxf(dcnt, 1e-8f);
    float res = fmaxf(acc/denom + g_SC[pt*64 + o], 0.f);
    out[((size_t)n*64 + o)*NP + p] = res;                 // transposed (N, 64, P)
}

// ---------------- launch ----------------
extern "C" void kernel_launch(void* const* d_in, const int* in_sizes, int n_in,
                              void* d_out, int out_size)
{
    const float* feats = (const float*)d_in[0];
    const unsigned char* mask = (const unsigned char*)d_in[1];
    const float* W0 = (const float*)d_in[2];
    const float* W1 = (const float*)d_in[3];
    const float* W2 = (const float*)d_in[4];
    const float* Ws = (const float*)d_in[5];

    fold_kernel<<<16, 256>>>(W1, W2,
        (const float*)d_in[6],  (const float*)d_in[7],  (const float*)d_in[8],  (const float*)d_in[9],
        (const float*)d_in[10], (const float*)d_in[11], (const float*)d_in[12], (const float*)d_in[13],
        (const float*)d_in[14], (const float*)d_in[15], (const float*)d_in[16], (const float*)d_in[17],
        (const float*)d_in[18], (const float*)d_in[19], (const float*)d_in[20], (const float*)d_in[21]);

    prep_kernel<<<NB*NP/4, 256>>>(feats, mask, W0, Ws);
    knn_kernel<<<NB*4, 256>>>(feats, mask);
    edge_kernel<<<NB*NP/4, 256>>>((float*)d_out);
}

// round 3
// speedup vs baseline: 1.4699x; 1.4699x over previous
#include <cuda_runtime.h>

#define NB 64
#define NP 1024
#define CF 16
#define KK 16
#define BN_EPS 1e-5f

// ---------------- static scratch (no allocations allowed) ----------------
__device__ float g_C [NB*NP*64];   // per-point center projection (BN-folded, pre-relu)
__device__ float g_Y [NB*NP*64];   // per-point neighbor projection (scaled)
__device__ float g_SC[NB*NP*64];   // shortcut (BN-folded, mask-zeroed)
__device__ int   g_idx[NB*NP*KK];  // knn indices
__device__ int   g_valid[NB];
__device__ float g_W1t[64*64];     // W1 (BN-scaled), TRANSPOSED: [c][o]
__device__ float g_W2t[64*64];     // W2 (BN-scaled), TRANSPOSED: [c][o]
__device__ float g_s0[64], g_t0[64], g_t1[64], g_t2[64], g_ss[64], g_ts[64];

// ---------------- fold BN into weights / biases ----------------
__global__ void fold_kernel(const float* __restrict__ W1, const float* __restrict__ W2,
    const float* g0,const float* b0,const float* m0,const float* v0,
    const float* g1,const float* b1,const float* m1,const float* v1,
    const float* g2,const float* b2,const float* m2,const float* v2,
    const float* gs,const float* bs,const float* ms,const float* vs)
{
    int t = blockIdx.x*blockDim.x + threadIdx.x;
    if (t < 64){
        float s0 = g0[t]*rsqrtf(v0[t]+BN_EPS); g_s0[t]=s0; g_t0[t]=b0[t]-m0[t]*s0;
        float s1 = g1[t]*rsqrtf(v1[t]+BN_EPS); g_t1[t]=b1[t]-m1[t]*s1;
        float s2 = g2[t]*rsqrtf(v2[t]+BN_EPS); g_t2[t]=b2[t]-m2[t]*s2;
        float ss = gs[t]*rsqrtf(vs[t]+BN_EPS); g_ss[t]=ss; g_ts[t]=bs[t]-ms[t]*ss;
    }
    if (t < 4096){
        int oo = t >> 6;          // output channel (row of W)
        int cc = t & 63;          // input channel  (col of W)
        g_W1t[cc*64 + oo] = W1[t]*(g1[oo]*rsqrtf(v1[oo]+BN_EPS));
        g_W2t[cc*64 + oo] = W2[t]*(g2[oo]*rsqrtf(v2[oo]+BN_EPS));
    }
}

// ---------------- per-point projections: C, Y, shortcut ----------------
// layer0: h@W0^T = x_p @ (W0a+W0b)^T - x_q @ W0b^T
__global__ void prep_kernel(const float* __restrict__ feats,
                            const unsigned char* __restrict__ mask,
                            const float* __restrict__ W0,
                            const float* __restrict__ Ws)
{
    const int lp = threadIdx.x >> 6;
    const int o  = threadIdx.x & 63;
    const int pt = blockIdx.x*4 + lp;
    __shared__ float sx[4][CF];
    if (o < CF) sx[lp][o] = feats[pt*(2+CF) + 2 + o];
    __syncthreads();
    float a = 0.f, yb = 0.f, sc = 0.f;
#pragma unroll
    for (int c = 0; c < CF; c++){
        float x  = sx[lp][c];
        float wa = W0[o*32 + c];
        float wb = W0[o*32 + 16 + c];
        a  = fmaf(x, wa + wb, a);
        yb = fmaf(x, wb, yb);
        sc = fmaf(x, Ws[o*16 + c], sc);
    }
    float s0 = g_s0[o];
    g_C[pt*64 + o] = fmaf(a, s0, g_t0[o]);
    g_Y[pt*64 + o] = yb*s0;
    float scv = fmaf(sc, g_ss[o], g_ts[o]);
    if (mask[pt]) scv = 0.f;
    g_SC[pt*64 + o] = scv;
}

// ---------------- KNN: top-16 by squared distance, excluding self ----------------
__global__ void knn_kernel(const float* __restrict__ feats,
                           const unsigned char* __restrict__ mask)
{
    const int n = blockIdx.x >> 2;
    const int p = ((blockIdx.x & 3) << 8) + threadIdx.x;
    __shared__ float px[NP], py[NP], rr[NP];
    __shared__ int scnt;
    if (threadIdx.x == 0) scnt = 0;
    __syncthreads();
    int mcnt = 0;
    for (int i = threadIdx.x; i < NP; i += 256){
        float x = feats[(n*NP + i)*(2+CF) + 0];
        float y = feats[(n*NP + i)*(2+CF) + 1];
        px[i] = x; py[i] = y; rr[i] = x*x + y*y;
        if (mask[n*NP + i]) mcnt++;
    }
    if (mcnt) atomicAdd(&scnt, mcnt);
    __syncthreads();
    if (threadIdx.x == 0 && (blockIdx.x & 3) == 0) g_valid[n] = NP - scnt;

    const float xp = px[p], yp = py[p], rp = rr[p];
    const float nx = -2.f*xp, ny = -2.f*yp;
    float bd[KK]; int bi[KK];
#pragma unroll
    for (int j = 0; j < KK; j++){ bd[j] = 3.4e38f; bi[j] = 0; }
    float worst = 3.4e38f; int ws = 0;
    for (int q = 0; q < NP; q++){
        float d = fmaf(nx, px[q], fmaf(ny, py[q], rp + rr[q]));
        if (d < worst && q != p){
#pragma unroll
            for (int j = 0; j < KK; j++) if (j == ws){ bd[j] = d; bi[j] = q; }
            worst = -1.f;
#pragma unroll
            for (int j = 0; j < KK; j++) if (bd[j] > worst){ worst = bd[j]; ws = j; }
        }
    }
#pragma unroll
    for (int j = 0; j < KK; j++) g_idx[(n*NP + p)*KK + j] = bi[j];
}

// ---------------- edge kernel: fused register-tiled GEMM ----------------
// Block = 4 points = 64 edge-rows (M=64). Two 64x64 layers as M64xN64xK64
// register-tiled GEMMs: thread tile 4M x 4N. Activations in SMEM [c][m]
// (1 LDS.128 / 16 FMA), weights via read-only LDG broadcast from L1-resident
// transposed matrices (1 LDG.128 / 16 FMA). All reductions race-free and
// deterministic (no atomics).
__global__ void __launch_bounds__(256)
edge_kernel(float* __restrict__ out)
{
    const int tid = threadIdx.x;
    const int pt0 = blockIdx.x * 4;
    const int n   = pt0 >> 10;

    __shared__ float act[64*64];     // [c][m], reused between layers
    __shared__ float validf[64];     // per-edge mask (1.0 valid / 0.0 masked)
    __shared__ float part[16*64];    // per (mt, channel) partial sums
    __shared__ float vcnt[4];        // per point valid-neighbor count

    const int valid = g_valid[n];

    // ---- phase 0: layer0 activations into act[c][m] ----
    {
        const int m  = tid >> 2;                 // edge row 0..63
        const int qu = tid & 3;                  // channel quarter
        const int pt = pt0 + (m >> 4);
        const int q  = g_idx[pt*KK + (m & 15)];
        if (qu == 0) validf[m] = (q < valid) ? 1.f : 0.f;
        const float4* Yq = (const float4*)(g_Y + ((size_t)n*NP + q)*64) + qu*4;
        const float4* Cp = (const float4*)(g_C + (size_t)pt*64) + qu*4;
#pragma unroll
        for (int j = 0; j < 4; j++){
            float4 y = Yq[j];
            float4 c = Cp[j];
            int cc = qu*16 + j*4;
            act[(cc+0)*64 + m] = fmaxf(c.x - y.x, 0.f);
            act[(cc+1)*64 + m] = fmaxf(c.y - y.y, 0.f);
            act[(cc+2)*64 + m] = fmaxf(c.z - y.z, 0.f);
            act[(cc+3)*64 + m] = fmaxf(c.w - y.w, 0.f);
        }
    }
    __syncthreads();

    // valid-neighbor counts (race-free: validf complete, vcnt read only after
    // later barriers)
    if (tid < 4){
        float s = 0.f;
#pragma unroll
        for (int j = 0; j < 16; j++) s += validf[tid*16 + j];
        vcnt[tid] = s;
    }

    // ---- GEMM tiling: thread = 4 M-rows x 4 N-cols ----
    const int mt = tid & 15;          // 16 M-tiles
    const int ot = tid >> 4;          // 16 N-tiles
    const int m0 = mt * 4;
    const int o0 = ot * 4;

    float acc[16];

    // ===== layer 1 =====
#pragma unroll
    for (int i = 0; i < 16; i++) acc[i] = 0.f;
    {
        const float4* B = (const float4*)g_W1t + ot;    // row c at B[c*16]
#pragma unroll 16
        for (int c = 0; c < 64; c++){
            float4 a = *(const float4*)(act + c*64 + m0);
            float4 b = __ldg(&B[c*16]);
            acc[ 0] = fmaf(a.x, b.x, acc[ 0]);
            acc[ 1] = fmaf(a.x, b.y, acc[ 1]);
            acc[ 2] = fmaf(a.x, b.z, acc[ 2]);
            acc[ 3] = fmaf(a.x, b.w, acc[ 3]);
            acc[ 4] = fmaf(a.y, b.x, acc[ 4]);
            acc[ 5] = fmaf(a.y, b.y, acc[ 5]);
            acc[ 6] = fmaf(a.y, b.z, acc[ 6]);
            acc[ 7] = fmaf(a.y, b.w, acc[ 7]);
            acc[ 8] = fmaf(a.z, b.x, acc[ 8]);
            acc[ 9] = fmaf(a.z, b.y, acc[ 9]);
            acc[10] = fmaf(a.z, b.z, acc[10]);
            acc[11] = fmaf(a.z, b.w, acc[11]);
            acc[12] = fmaf(a.w, b.x, acc[12]);
            acc[13] = fmaf(a.w, b.y, acc[13]);
            acc[14] = fmaf(a.w, b.z, acc[14]);
            acc[15] = fmaf(a.w, b.w, acc[15]);
        }
    }
    __syncthreads();   // everyone finished reading act

    {
        float t1v0 = g_t1[o0+0], t1v1 = g_t1[o0+1], t1v2 = g_t1[o0+2], t1v3 = g_t1[o0+3];
#pragma unroll
        for (int mi = 0; mi < 4; mi++){
            act[(o0+0)*64 + m0+mi] = fmaxf(acc[mi*4+0] + t1v0, 0.f);
            act[(o0+1)*64 + m0+mi] = fmaxf(acc[mi*4+1] + t1v1, 0.f);
            act[(o0+2)*64 + m0+mi] = fmaxf(acc[mi*4+2] + t1v2, 0.f);
            act[(o0+3)*64 + m0+mi] = fmaxf(acc[mi*4+3] + t1v3, 0.f);
        }
    }
    __syncthreads();   // layer-1 activations ready

    // ===== layer 2 =====
#pragma unroll
    for (int i = 0; i < 16; i++) acc[i] = 0.f;
    {
        const float4* B = (const float4*)g_W2t + ot;
#pragma unroll 16
        for (int c = 0; c < 64; c++){
            float4 a = *(const float4*)(act + c*64 + m0);
            float4 b = __ldg(&B[c*16]);
            acc[ 0] = fmaf(a.x, b.x, acc[ 0]);
            acc[ 1] = fmaf(a.x, b.y, acc[ 1]);
            acc[ 2] = fmaf(a.x, b.z, acc[ 2]);
            acc[ 3] = fmaf(a.x, b.w, acc[ 3]);
            acc[ 4] = fmaf(a.y, b.x, acc[ 4]);
            acc[ 5] = fmaf(a.y, b.y, acc[ 5]);
            acc[ 6] = fmaf(a.y, b.z, acc[ 6]);
            acc[ 7] = fmaf(a.y, b.w, acc[ 7]);
            acc[ 8] = fmaf(a.z, b.x, acc[ 8]);
            acc[ 9] = fmaf(a.z, b.y, acc[ 9]);
            acc[10] = fmaf(a.z, b.z, acc[10]);
            acc[11] = fmaf(a.z, b.w, acc[11]);
            acc[12] = fmaf(a.w, b.x, acc[12]);
            acc[13] = fmaf(a.w, b.y, acc[13]);
            acc[14] = fmaf(a.w, b.z, acc[14]);
            acc[15] = fmaf(a.w, b.w, acc[15]);
        }
    }

    // ===== epilogue: relu + masked partial sums into private slots =====
    {
        float t2v0 = g_t2[o0+0], t2v1 = g_t2[o0+1], t2v2 = g_t2[o0+2], t2v3 = g_t2[o0+3];
        float vf0 = validf[m0+0], vf1 = validf[m0+1], vf2 = validf[m0+2], vf3 = validf[m0+3];
        part[mt*64 + o0+0] = fmaxf(acc[ 0]+t2v0,0.f)*vf0 + fmaxf(acc[ 4]+t2v0,0.f)*vf1
                           + fmaxf(acc[ 8]+t2v0,0.f)*vf2 + fmaxf(acc[12]+t2v0,0.f)*vf3;
        part[mt*64 + o0+1] = fmaxf(acc[ 1]+t2v1,0.f)*vf0 + fmaxf(acc[ 5]+t2v1,0.f)*vf1
                           + fmaxf(acc[ 9]+t2v1,0.f)*vf2 + fmaxf(acc[13]+t2v1,0.f)*vf3;
        part[mt*64 + o0+2] = fmaxf(acc[ 2]+t2v2,0.f)*vf0 + fmaxf(acc[ 6]+t2v2,0.f)*vf1
                           + fmaxf(acc[10]+t2v2,0.f)*vf2 + fmaxf(acc[14]+t2v2,0.f)*vf3;
        part[mt*64 + o0+3] = fmaxf(acc[ 3]+t2v3,0.f)*vf0 + fmaxf(acc[ 7]+t2v3,0.f)*vf1
                           + fmaxf(acc[11]+t2v3,0.f)*vf2 + fmaxf(acc[15]+t2v3,0.f)*vf3;
    }
    __syncthreads();

    // ===== final: deterministic 4-way sum + mean + shortcut + relu, transposed store =====
    {
        const int o  = tid >> 2;          // channel
        const int pl = tid & 3;           // local point
        const int pt = pt0 + pl;
        const int p  = pt & (NP-1);
        float s = part[(pl*4+0)*64 + o] + part[(pl*4+1)*64 + o]
                + part[(pl*4+2)*64 + o] + part[(pl*4+3)*64 + o];
        float denom = fmaxf(vcnt[pl], 1e-8f);
        float res = fmaxf(s/denom + g_SC[(size_t)pt*64 + o], 0.f);
        out[((size_t)n*64 + o)*NP + p] = res;
    }
}

// ---------------- launch ----------------
extern "C" void kernel_launch(void* const* d_in, const int* in_sizes, int n_in,
                              void* d_out, int out_size)
{
    const float* feats = (const float*)d_in[0];
    const unsigned char* mask = (const unsigned char*)d_in[1];
    const float* W0 = (const float*)d_in[2];
    const float* W1 = (const float*)d_in[3];
    const float* W2 = (const float*)d_in[4];
    const float* Ws = (const float*)d_in[5];

    fold_kernel<<<16, 256>>>(W1, W2,
        (const float*)d_in[6],  (const float*)d_in[7],  (const float*)d_in[8],  (const float*)d_in[9],
        (const float*)d_in[10], (const float*)d_in[11], (const float*)d_in[12], (const float*)d_in[13],
        (const float*)d_in[14], (const float*)d_in[15], (const float*)d_in[16], (const float*)d_in[17],
        (const float*)d_in[18], (const float*)d_in[19], (const float*)d_in[20], (const float*)d_in[21]);

    prep_kernel<<<NB*NP/4, 256>>>(feats, mask, W0, Ws);
    knn_kernel<<<NB*4, 256>>>(feats, mask);
    edge_kernel<<<NB*NP/4, 256>>>((float*)d_out);
}

// round 4
// speedup vs baseline: 1.8499x; 1.2585x over previous
#include <cuda_runtime.h>

#define NB 64
#define NP 1024
#define CF 16
#define KK 16
#define BN_EPS 1e-5f

// ---------------- static scratch (no allocations allowed) ----------------
__device__ float g_C [NB*NP*64];   // per-point center projection (BN-folded, pre-relu)
__device__ float g_Y [NB*NP*64];   // per-point neighbor projection (scaled)
__device__ float g_SC[NB*NP*64];   // shortcut (BN-folded, mask-zeroed)
__device__ int   g_idx[NB*NP*KK];  // knn indices
__device__ int   g_valid[NB];
__device__ float g_W1t[64*64];     // W1 (BN-scaled), TRANSPOSED: [c][o]
__device__ float g_W2t[64*64];     // W2 (BN-scaled), TRANSPOSED: [c][o]
__device__ float g_s0[64], g_t0[64], g_t1[64], g_t2[64], g_ss[64], g_ts[64];

// ---------------- fold BN into weights / biases ----------------
__global__ void fold_kernel(const float* __restrict__ W1, const float* __restrict__ W2,
    const float* g0,const float* b0,const float* m0,const float* v0,
    const float* g1,const float* b1,const float* m1,const float* v1,
    const float* g2,const float* b2,const float* m2,const float* v2,
    const float* gs,const float* bs,const float* ms,const float* vs)
{
    int t = blockIdx.x*blockDim.x + threadIdx.x;
    if (t < 64){
        float s0 = g0[t]*rsqrtf(v0[t]+BN_EPS); g_s0[t]=s0; g_t0[t]=b0[t]-m0[t]*s0;
        float s1 = g1[t]*rsqrtf(v1[t]+BN_EPS); g_t1[t]=b1[t]-m1[t]*s1;
        float s2 = g2[t]*rsqrtf(v2[t]+BN_EPS); g_t2[t]=b2[t]-m2[t]*s2;
        float ss = gs[t]*rsqrtf(vs[t]+BN_EPS); g_ss[t]=ss; g_ts[t]=bs[t]-ms[t]*ss;
    }
    if (t < 4096){
        int oo = t >> 6;          // output channel (row of W)
        int cc = t & 63;          // input channel  (col of W)
        g_W1t[cc*64 + oo] = W1[t]*(g1[oo]*rsqrtf(v1[oo]+BN_EPS));
        g_W2t[cc*64 + oo] = W2[t]*(g2[oo]*rsqrtf(v2[oo]+BN_EPS));
    }
}

// ---------------- per-point projections: C, Y, shortcut ----------------
// layer0: h@W0^T = x_p @ (W0a+W0b)^T - x_q @ W0b^T
__global__ void prep_kernel(const float* __restrict__ feats,
                            const unsigned char* __restrict__ mask,
                            const float* __restrict__ W0,
                            const float* __restrict__ Ws)
{
    const int lp = threadIdx.x >> 6;
    const int o  = threadIdx.x & 63;
    const int pt = blockIdx.x*4 + lp;
    __shared__ float sx[4][CF];
    if (o < CF) sx[lp][o] = feats[pt*(2+CF) + 2 + o];
    __syncthreads();
    float a = 0.f, yb = 0.f, sc = 0.f;
#pragma unroll
    for (int c = 0; c < CF; c++){
        float x  = sx[lp][c];
        float wa = W0[o*32 + c];
        float wb = W0[o*32 + 16 + c];
        a  = fmaf(x, wa + wb, a);
        yb = fmaf(x, wb, yb);
        sc = fmaf(x, Ws[o*16 + c], sc);
    }
    float s0 = g_s0[o];
    g_C[pt*64 + o] = fmaf(a, s0, g_t0[o]);
    g_Y[pt*64 + o] = yb*s0;
    float scv = fmaf(sc, g_ss[o], g_ts[o]);
    if (mask[pt]) scv = 0.f;
    g_SC[pt*64 + o] = scv;
}

// ---------------- KNN v2: warp-per-point, branch-free ----------------
// Each lane owns 32 candidates as packed keys (d_bits | q). In-register
// bitonic sort (fully unrolled, no divergence), then a 16-round heads merge
// across the warp via shfl-min. Block = 8 warps = 8 points.
__global__ void __launch_bounds__(256)
knn_kernel(const float* __restrict__ feats,
           const unsigned char* __restrict__ mask)
{
    const int n    = blockIdx.x >> 7;          // 128 blocks per batch
    const int bloc = blockIdx.x & 127;
    const int warp = threadIdx.x >> 5;
    const int lane = threadIdx.x & 31;
    const int p    = bloc*8 + warp;

    __shared__ float px[NP], py[NP], rr[NP];
    __shared__ unsigned int heads[8][512];     // [warp][j*32 + lane]
    __shared__ int scnt;

    if (threadIdx.x == 0) scnt = 0;
    int mcnt = 0;
    for (int i = threadIdx.x; i < NP; i += 256){
        float x = feats[(n*NP + i)*(2+CF) + 0];
        float y = feats[(n*NP + i)*(2+CF) + 1];
        px[i] = x; py[i] = y; rr[i] = x*x + y*y;
        if (bloc == 0 && mask[n*NP + i]) mcnt++;
    }
    __syncthreads();
    if (bloc == 0 && mcnt) atomicAdd(&scnt, mcnt);

    const float xp = px[p], yp = py[p], rp = rr[p];
    const float nx = -2.f*xp, ny = -2.f*yp;

    unsigned int key[32];
#pragma unroll
    for (int i = 0; i < 32; i++){
        int q = i*32 + lane;
        float d = fmaxf(fmaf(nx, px[q], fmaf(ny, py[q], rp + rr[q])), 0.f);
        unsigned int kb = (__float_as_uint(d) & 0xFFFFFC00u) | (unsigned int)q;
        key[i] = (q == p) ? 0xFFFFFFFFu : kb;
    }

    // in-register bitonic sort, ascending (all indices compile-time)
#pragma unroll
    for (int kk = 2; kk <= 32; kk <<= 1){
#pragma unroll
        for (int j = kk >> 1; j > 0; j >>= 1){
#pragma unroll
            for (int i = 0; i < 32; i++){
                int l = i ^ j;
                if (l > i){
                    unsigned int a = key[i], b = key[l];
                    unsigned int lo = a < b ? a : b;
                    unsigned int hi = a < b ? b : a;
                    if ((i & kk) == 0){ key[i] = lo; key[l] = hi; }
                    else              { key[i] = hi; key[l] = lo; }
                }
            }
        }
    }

    // park sorted top-16 in this lane's private SMEM column
#pragma unroll
    for (int j = 0; j < 16; j++) heads[warp][j*32 + lane] = key[j];

    // 16-round heads merge (lane's ptr indexes only its own column; the
    // cross-lane communication is the shfl reduction)
    int ptr = 0;
    unsigned int sel = 0;
#pragma unroll 1
    for (int r = 0; r < KK; r++){
        unsigned int h = (ptr < 16) ? heads[warp][ptr*32 + lane] : 0xFFFFFFFFu;
        unsigned int w = h;
#pragma unroll
        for (int d = 16; d; d >>= 1){
            unsigned int o = __shfl_xor_sync(0xFFFFFFFFu, w, d);
            w = (o < w) ? o : w;
        }
        if (h == w) ptr++;          // keys unique (q embedded) -> one owner
        if (lane == r) sel = w;
    }
    if (lane < KK) g_idx[(n*NP + p)*KK + lane] = (int)(sel & 1023u);

    if (bloc == 0){
        __syncthreads();
        if (threadIdx.x == 0) g_valid[n] = NP - scnt;
    }
}

// ---------------- edge kernel v2: M=128 per block, thread tile 4M x 8N ----------------
// Per k-step: 1 LDS.128 (4 M-activations) + 2 warp-uniform LDG.128 (8 weights)
// feed 32 FMAs. Layer-1 writeback via STS.128. Deterministic, atomic-free.
__global__ void __launch_bounds__(256)
edge_kernel(float* __restrict__ out)
{
    const int tid = threadIdx.x;
    const int pt0 = blockIdx.x * 8;          // 8 points per block
    const int n   = pt0 >> 10;

    __shared__ float act[64*128];            // [c][m], reused between layers
    __shared__ float part[32*64];            // [mt][o] partial sums
    __shared__ float validf[128];
    __shared__ float vcnt[8];

    const int valid = g_valid[n];

    // ---- phase 0: layer-0 activations into act[c][m] ----
    {
        const int m  = tid >> 1;             // edge row 0..127
        const int h  = tid & 1;              // channel half
        const int pt = pt0 + (m >> 4);
        const int q  = g_idx[pt*KK + (m & 15)];
        if (h == 0) validf[m] = (q < valid) ? 1.f : 0.f;
        const float4* Yq = (const float4*)(g_Y + ((size_t)n*NP + q)*64) + h*8;
        const float4* Cp = (const float4*)(g_C + (size_t)pt*64) + h*8;
#pragma unroll
        for (int j = 0; j < 8; j++){
            float4 y = Yq[j];
            float4 c = Cp[j];
            int cc = h*32 + j*4;
            act[(cc+0)*128 + m] = fmaxf(c.x - y.x, 0.f);
            act[(cc+1)*128 + m] = fmaxf(c.y - y.y, 0.f);
            act[(cc+2)*128 + m] = fmaxf(c.z - y.z, 0.f);
            act[(cc+3)*128 + m] = fmaxf(c.w - y.w, 0.f);
        }
    }
    __syncthreads();

    if (tid < 8){
        float s = 0.f;
#pragma unroll
        for (int j = 0; j < 16; j++) s += validf[tid*16 + j];
        vcnt[tid] = s;
    }

    // ---- GEMM tiling: 32 M-tiles x 8 N-tiles ----
    const int mt = tid & 31;
    const int ot = tid >> 5;
    const int m0 = mt * 4;
    const int o0 = ot * 8;

    float acc[32];

    // ===== layer 1 =====
#pragma unroll
    for (int i = 0; i < 32; i++) acc[i] = 0.f;
    {
        const float4* B = (const float4*)g_W1t + ot*2;
#pragma unroll 8
        for (int c = 0; c < 64; c++){
            float4 a  = *(const float4*)(act + c*128 + m0);
            float4 b0 = __ldg(B + c*16);
            float4 b1 = __ldg(B + c*16 + 1);
            acc[ 0]=fmaf(a.x,b0.x,acc[ 0]); acc[ 1]=fmaf(a.x,b0.y,acc[ 1]);
            acc[ 2]=fmaf(a.x,b0.z,acc[ 2]); acc[ 3]=fmaf(a.x,b0.w,acc[ 3]);
            acc[ 4]=fmaf(a.x,b1.x,acc[ 4]); acc[ 5]=fmaf(a.x,b1.y,acc[ 5]);
            acc[ 6]=fmaf(a.x,b1.z,acc[ 6]); acc[ 7]=fmaf(a.x,b1.w,acc[ 7]);
            acc[ 8]=fmaf(a.y,b0.x,acc[ 8]); acc[ 9]=fmaf(a.y,b0.y,acc[ 9]);
            acc[10]=fmaf(a.y,b0.z,acc[10]); acc[11]=fmaf(a.y,b0.w,acc[11]);
            acc[12]=fmaf(a.y,b1.x,acc[12]); acc[13]=fmaf(a.y,b1.y,acc[13]);
            acc[14]=fmaf(a.y,b1.z,acc[14]); acc[15]=fmaf(a.y,b1.w,acc[15]);
            acc[16]=fmaf(a.z,b0.x,acc[16]); acc[17]=fmaf(a.z,b0.y,acc[17]);
            acc[18]=fmaf(a.z,b0.z,acc[18]); acc[19]=fmaf(a.z,b0.w,acc[19]);
            acc[20]=fmaf(a.z,b1.x,acc[20]); acc[21]=fmaf(a.z,b1.y,acc[21]);
            acc[22]=fmaf(a.z,b1.z,acc[22]); acc[23]=fmaf(a.z,b1.w,acc[23]);
            acc[24]=fmaf(a.w,b0.x,acc[24]); acc[25]=fmaf(a.w,b0.y,acc[25]);
            acc[26]=fmaf(a.w,b0.z,acc[26]); acc[27]=fmaf(a.w,b0.w,acc[27]);
            acc[28]=fmaf(a.w,b1.x,acc[28]); acc[29]=fmaf(a.w,b1.y,acc[29]);
            acc[30]=fmaf(a.w,b1.z,acc[30]); acc[31]=fmaf(a.w,b1.w,acc[31]);
        }
    }
    __syncthreads();   // all reads of act complete

    // bias + relu, write back transposed via STS.128
#pragma unroll
    for (int oi = 0; oi < 8; oi++){
        float t1 = g_t1[o0 + oi];
        float4 v;
        v.x = fmaxf(acc[ 0 + oi] + t1, 0.f);
        v.y = fmaxf(acc[ 8 + oi] + t1, 0.f);
        v.z = fmaxf(acc[16 + oi] + t1, 0.f);
        v.w = fmaxf(acc[24 + oi] + t1, 0.f);
        *(float4*)(act + (o0 + oi)*128 + m0) = v;
    }
    __syncthreads();   // layer-1 activations ready

    // ===== layer 2 =====
#pragma unroll
    for (int i = 0; i < 32; i++) acc[i] = 0.f;
    {
        const float4* B = (const float4*)g_W2t + ot*2;
#pragma unroll 8
        for (int c = 0; c < 64; c++){
            float4 a  = *(const float4*)(act + c*128 + m0);
            float4 b0 = __ldg(B + c*16);
            float4 b1 = __ldg(B + c*16 + 1);
            acc[ 0]=fmaf(a.x,b0.x,acc[ 0]); acc[ 1]=fmaf(a.x,b0.y,acc[ 1]);
            acc[ 2]=fmaf(a.x,b0.z,acc[ 2]); acc[ 3]=fmaf(a.x,b0.w,acc[ 3]);
            acc[ 4]=fmaf(a.x,b1.x,acc[ 4]); acc[ 5]=fmaf(a.x,b1.y,acc[ 5]);
            acc[ 6]=fmaf(a.x,b1.z,acc[ 6]); acc[ 7]=fmaf(a.x,b1.w,acc[ 7]);
            acc[ 8]=fmaf(a.y,b0.x,acc[ 8]); acc[ 9]=fmaf(a.y,b0.y,acc[ 9]);
            acc[10]=fmaf(a.y,b0.z,acc[10]); acc[11]=fmaf(a.y,b0.w,acc[11]);
            acc[12]=fmaf(a.y,b1.x,acc[12]); acc[13]=fmaf(a.y,b1.y,acc[13]);
            acc[14]=fmaf(a.y,b1.z,acc[14]); acc[15]=fmaf(a.y,b1.w,acc[15]);
            acc[16]=fmaf(a.z,b0.x,acc[16]); acc[17]=fmaf(a.z,b0.y,acc[17]);
            acc[18]=fmaf(a.z,b0.z,acc[18]); acc[19]=fmaf(a.z,b0.w,acc[19]);
            acc[20]=fmaf(a.z,b1.x,acc[20]); acc[21]=fmaf(a.z,b1.y,acc[21]);
            acc[22]=fmaf(a.z,b1.z,acc[22]); acc[23]=fmaf(a.z,b1.w,acc[23]);
            acc[24]=fmaf(a.w,b0.x,acc[24]); acc[25]=fmaf(a.w,b0.y,acc[25]);
            acc[26]=fmaf(a.w,b0.z,acc[26]); acc[27]=fmaf(a.w,b0.w,acc[27]);
            acc[28]=fmaf(a.w,b1.x,acc[28]); acc[29]=fmaf(a.w,b1.y,acc[29]);
            acc[30]=fmaf(a.w,b1.z,acc[30]); acc[31]=fmaf(a.w,b1.w,acc[31]);
        }
    }

    // ===== epilogue: relu + masked per-point partials (rows of one point) =====
    {
        const float vf0 = validf[m0+0], vf1 = validf[m0+1];
        const float vf2 = validf[m0+2], vf3 = validf[m0+3];
#pragma unroll
        for (int oi = 0; oi < 8; oi++){
            float t2 = g_t2[o0 + oi];
            float s = fmaxf(acc[ 0+oi]+t2, 0.f)*vf0
                    + fmaxf(acc[ 8+oi]+t2, 0.f)*vf1
                    + fmaxf(acc[16+oi]+t2, 0.f)*vf2
                    + fmaxf(acc[24+oi]+t2, 0.f)*vf3;
            part[mt*64 + o0 + oi] = s;
        }
    }
    __syncthreads();

    // ===== final: deterministic 4-way sum + mean + shortcut + relu =====
#pragma unroll
    for (int s = 0; s < 2; s++){
        const int idx = tid + s*256;         // 512 outputs: 8 points x 64 ch
        const int o   = idx >> 3;
        const int pl  = idx & 7;
        const int pt  = pt0 + pl;
        const int p   = pt & (NP-1);
        float sum = part[(pl*4+0)*64 + o] + part[(pl*4+1)*64 + o]
                  + part[(pl*4+2)*64 + o] + part[(pl*4+3)*64 + o];
        float denom = fmaxf(vcnt[pl], 1e-8f);
        float res = fmaxf(sum/denom + g_SC[(size_t)pt*64 + o], 0.f);
        out[((size_t)n*64 + o)*NP + p] = res;
    }
}

// ---------------- launch ----------------
extern "C" void kernel_launch(void* const* d_in, const int* in_sizes, int n_in,
                              void* d_out, int out_size)
{
    const float* feats = (const float*)d_in[0];
    const unsigned char* mask = (const unsigned char*)d_in[1];
    const float* W0 = (const float*)d_in[2];
    const float* W1 = (const float*)d_in[3];
    const float* W2 = (const float*)d_in[4];
    const float* Ws = (const float*)d_in[5];

    fold_kernel<<<16, 256>>>(W1, W2,
        (const float*)d_in[6],  (const float*)d_in[7],  (const float*)d_in[8],  (const float*)d_in[9],
        (const float*)d_in[10], (const float*)d_in[11], (const float*)d_in[12], (const float*)d_in[13],
        (const float*)d_in[14], (const float*)d_in[15], (const float*)d_in[16], (const float*)d_in[17],
        (const float*)d_in[18], (const float*)d_in[19], (const float*)d_in[20], (const float*)d_in[21]);

    prep_kernel<<<NB*NP/4, 256>>>(feats, mask, W0, Ws);
    knn_kernel<<<NB*128, 256>>>(feats, mask);
    edge_kernel<<<NB*NP/8, 256>>>((float*)d_out);
}

// round 5
// speedup vs baseline: 3.2936x; 1.7804x over previous
#include <cuda_runtime.h>

#define NB 64
#define NP 1024
#define CF 16
#define KK 16
#define BN_EPS 1e-5f

typedef unsigned long long u64;

#define FMA2(d, a, b, c) \
    asm("fma.rn.f32x2 %0, %1, %2, %3;" : "=l"(d) : "l"(a), "l"(b), "l"(c))
#define PACK2(d, x) \
    asm("mov.b64 %0, {%1, %1};" : "=l"(d) : "f"(x))
#define UNPACK2(lo, hi, v) \
    asm("mov.b64 {%0, %1}, %2;" : "=f"(lo), "=f"(hi) : "l"(v))

// ---------------- static scratch (no allocations allowed) ----------------
__device__ float g_C [NB*NP*64];   // per-point center projection (BN-folded)
__device__ float g_Y [NB*NP*64];   // per-point neighbor projection (scaled)
__device__ float g_SC[NB*NP*64];   // shortcut (BN-folded, mask-zeroed)
__device__ int   g_idx[NB*NP*KK];  // knn indices
__device__ int   g_valid[NB];
__device__ float g_W1t[64*64];     // W1 (BN-scaled), TRANSPOSED: [c][o]
__device__ float g_W2t[64*64];     // W2 (BN-scaled), TRANSPOSED: [c][o]
__device__ float g_W0at[CF*64];    // (W0a+W0b)*s0, transposed [c][o]
__device__ float g_W0bt[CF*64];    // W0b*s0, transposed [c][o]
__device__ float g_Wst [CF*64];    // Ws*ss, transposed [c][o]
__device__ float g_t0[64], g_t1[64], g_t2[64], g_ts[64];

// ---------------- fold BN into weights / biases ----------------
__global__ void fold_kernel(const float* __restrict__ W0, const float* __restrict__ W1,
    const float* __restrict__ W2, const float* __restrict__ Ws,
    const float* g0,const float* b0,const float* m0,const float* v0,
    const float* g1,const float* b1,const float* m1,const float* v1,
    const float* g2,const float* b2,const float* m2,const float* v2,
    const float* gs,const float* bs,const float* ms,const float* vs)
{
    int t = blockIdx.x*blockDim.x + threadIdx.x;
    if (t < 64){
        float s0 = g0[t]*rsqrtf(v0[t]+BN_EPS); g_t0[t]=b0[t]-m0[t]*s0;
        float s1 = g1[t]*rsqrtf(v1[t]+BN_EPS); g_t1[t]=b1[t]-m1[t]*s1;
        float s2 = g2[t]*rsqrtf(v2[t]+BN_EPS); g_t2[t]=b2[t]-m2[t]*s2;
        float ss = gs[t]*rsqrtf(vs[t]+BN_EPS); g_ts[t]=bs[t]-ms[t]*ss;
    }
    if (t < 1024){                 // W0 (64x32) and Ws (64x16) -> transposed, folded
        int o = t >> 4;
        int c = t & 15;
        float s0 = g0[o]*rsqrtf(v0[o]+BN_EPS);
        float ss = gs[o]*rsqrtf(vs[o]+BN_EPS);
        float wa = W0[o*32 + c];
        float wb = W0[o*32 + 16 + c];
        g_W0at[c*64 + o] = (wa + wb)*s0;
        g_W0bt[c*64 + o] = wb*s0;
        g_Wst [c*64 + o] = Ws[o*16 + c]*ss;
    }
    if (t < 4096){
        int oo = t >> 6;
        int cc = t & 63;
        g_W1t[cc*64 + oo] = W1[t]*(g1[oo]*rsqrtf(v1[oo]+BN_EPS));
        g_W2t[cc*64 + oo] = W2[t]*(g2[oo]*rsqrtf(v2[oo]+BN_EPS));
    }
}

// ---------------- per-point projections: C, Y, shortcut (coalesced) ----------------
__global__ void prep_kernel(const float* __restrict__ feats,
                            const unsigned char* __restrict__ mask)
{
    const int lp = threadIdx.x >> 6;
    const int o  = threadIdx.x & 63;
    const int pt = blockIdx.x*4 + lp;
    __shared__ float sx[4][CF];
    if (o < CF) sx[lp][o] = feats[pt*(2+CF) + 2 + o];
    __syncthreads();
    float a = 0.f, yb = 0.f, sc = 0.f;
#pragma unroll
    for (int c = 0; c < CF; c++){
        float x = sx[lp][c];
        a  = fmaf(x, g_W0at[c*64 + o], a);     // lane-contiguous: 1 wavefront
        yb = fmaf(x, g_W0bt[c*64 + o], yb);
        sc = fmaf(x, g_Wst [c*64 + o], sc);
    }
    g_C[pt*64 + o] = a + g_t0[o];
    g_Y[pt*64 + o] = yb;
    float scv = sc + g_ts[o];
    if (mask[pt]) scv = 0.f;
    g_SC[pt*64 + o] = scv;
}

// ---------------- KNN: warp-per-point, branch-free bitonic ----------------
__global__ void __launch_bounds__(256)
knn_kernel(const float* __restrict__ feats,
           const unsigned char* __restrict__ mask)
{
    const int n    = blockIdx.x >> 7;
    const int bloc = blockIdx.x & 127;
    const int warp = threadIdx.x >> 5;
    const int lane = threadIdx.x & 31;
    const int p    = bloc*8 + warp;

    __shared__ float px[NP], py[NP], rr[NP];
    __shared__ unsigned int heads[8][512];
    __shared__ int scnt;

    if (threadIdx.x == 0) scnt = 0;
    int mcnt = 0;
    for (int i = threadIdx.x; i < NP; i += 256){
        float x = feats[(n*NP + i)*(2+CF) + 0];
        float y = feats[(n*NP + i)*(2+CF) + 1];
        px[i] = x; py[i] = y; rr[i] = x*x + y*y;
        if (bloc == 0 && mask[n*NP + i]) mcnt++;
    }
    __syncthreads();
    if (bloc == 0 && mcnt) atomicAdd(&scnt, mcnt);

    const float xp = px[p], yp = py[p], rp = rr[p];
    const float nx = -2.f*xp, ny = -2.f*yp;

    unsigned int key[32];
#pragma unroll
    for (int i = 0; i < 32; i++){
        int q = i*32 + lane;
        float d = fmaxf(fmaf(nx, px[q], fmaf(ny, py[q], rp + rr[q])), 0.f);
        unsigned int kb = (__float_as_uint(d) & 0xFFFFFC00u) | (unsigned int)q;
        key[i] = (q == p) ? 0xFFFFFFFFu : kb;
    }

#pragma unroll
    for (int kk = 2; kk <= 32; kk <<= 1){
#pragma unroll
        for (int j = kk >> 1; j > 0; j >>= 1){
#pragma unroll
            for (int i = 0; i < 32; i++){
                int l = i ^ j;
                if (l > i){
                    unsigned int a = key[i], b = key[l];
                    unsigned int lo = a < b ? a : b;
                    unsigned int hi = a < b ? b : a;
                    if ((i & kk) == 0){ key[i] = lo; key[l] = hi; }
                    else              { key[i] = hi; key[l] = lo; }
                }
            }
        }
    }

#pragma unroll
    for (int j = 0; j < 16; j++) heads[warp][j*32 + lane] = key[j];

    int ptr = 0;
    unsigned int sel = 0;
#pragma unroll 1
    for (int r = 0; r < KK; r++){
        unsigned int h = (ptr < 16) ? heads[warp][ptr*32 + lane] : 0xFFFFFFFFu;
        unsigned int w = h;
#pragma unroll
        for (int d = 16; d; d >>= 1){
            unsigned int o = __shfl_xor_sync(0xFFFFFFFFu, w, d);
            w = (o < w) ? o : w;
        }
        if (h == w) ptr++;
        if (lane == r) sel = w;
    }
    if (lane < KK) g_idx[(n*NP + p)*KK + lane] = (int)(sel & 1023u);

    if (bloc == 0){
        __syncthreads();
        if (threadIdx.x == 0) g_valid[n] = NP - scnt;
    }
}

// ---------------- edge kernel v3: packed f32x2 FMA (FFMA2) ----------------
// Block = 8 points = 128 edge-rows. Thread tile 4M x 8N, N paired into f32x2:
// weight pairs and bias pairs load pre-packed from memory; only the
// activation scalar needs a dup-pack (4 per k-step, reused across 4 pairs).
__global__ void __launch_bounds__(256)
edge_kernel(float* __restrict__ out)
{
    const int tid = threadIdx.x;
    const int pt0 = blockIdx.x * 8;
    const int n   = pt0 >> 10;

    __shared__ float act[64*128];
    __shared__ float part[32*64];
    __shared__ float validf[128];
    __shared__ float vcnt[8];

    const int valid = g_valid[n];

    // ---- phase 0: layer-0 activations into act[c][m] ----
    {
        const int m  = tid >> 1;
        const int h  = tid & 1;
        const int pt = pt0 + (m >> 4);
        const int q  = g_idx[pt*KK + (m & 15)];
        if (h == 0) validf[m] = (q < valid) ? 1.f : 0.f;
        const float4* Yq = (const float4*)(g_Y + ((size_t)n*NP + q)*64) + h*8;
        const float4* Cp = (const float4*)(g_C + (size_t)pt*64) + h*8;
#pragma unroll
        for (int j = 0; j < 8; j++){
            float4 y = Yq[j];
            float4 c = Cp[j];
            int cc = h*32 + j*4;
            act[(cc+0)*128 + m] = fmaxf(c.x - y.x, 0.f);
            act[(cc+1)*128 + m] = fmaxf(c.y - y.y, 0.f);
            act[(cc+2)*128 + m] = fmaxf(c.z - y.z, 0.f);
            act[(cc+3)*128 + m] = fmaxf(c.w - y.w, 0.f);
        }
    }
    __syncthreads();

    if (tid < 8){
        float s = 0.f;
#pragma unroll
        for (int j = 0; j < 16; j++) s += validf[tid*16 + j];
        vcnt[tid] = s;
    }

    const int mt = tid & 31;
    const int ot = tid >> 5;
    const int m0 = mt * 4;
    const int o0 = ot * 8;

    // acc[mi*4 + oj] = packed outputs (o0+2oj, o0+2oj+1) for M-row m0+mi
    u64 acc[16];

    // ===== layer 1 =====
    {
        const u64* tp = (const u64*)(g_t1 + o0);     // pre-packed bias pairs
        u64 t0p = tp[0], t1p = tp[1], t2p = tp[2], t3p = tp[3];
#pragma unroll
        for (int mi = 0; mi < 4; mi++){
            acc[mi*4+0]=t0p; acc[mi*4+1]=t1p; acc[mi*4+2]=t2p; acc[mi*4+3]=t3p;
        }
        const float* W = g_W1t + o0;
#pragma unroll 8
        for (int c = 0; c < 64; c++){
            float4 a = *(const float4*)(act + c*128 + m0);
            u64 ax, ay, az, aw;
            PACK2(ax, a.x); PACK2(ay, a.y); PACK2(az, a.z); PACK2(aw, a.w);
            ulonglong2 b01 = __ldg((const ulonglong2*)(W + c*64));
            ulonglong2 b23 = __ldg((const ulonglong2*)(W + c*64 + 4));
            FMA2(acc[ 0], ax, b01.x, acc[ 0]); FMA2(acc[ 1], ax, b01.y, acc[ 1]);
            FMA2(acc[ 2], ax, b23.x, acc[ 2]); FMA2(acc[ 3], ax, b23.y, acc[ 3]);
            FMA2(acc[ 4], ay, b01.x, acc[ 4]); FMA2(acc[ 5], ay, b01.y, acc[ 5]);
            FMA2(acc[ 6], ay, b23.x, acc[ 6]); FMA2(acc[ 7], ay, b23.y, acc[ 7]);
            FMA2(acc[ 8], az, b01.x, acc[ 8]); FMA2(acc[ 9], az, b01.y, acc[ 9]);
            FMA2(acc[10], az, b23.x, acc[10]); FMA2(acc[11], az, b23.y, acc[11]);
            FMA2(acc[12], aw, b01.x, acc[12]); FMA2(acc[13], aw, b01.y, acc[13]);
            FMA2(acc[14], aw, b23.x, acc[14]); FMA2(acc[15], aw, b23.y, acc[15]);
        }
    }
    __syncthreads();   // all reads of act complete

    // relu + transposed writeback via STS.128
#pragma unroll
    for (int oj = 0; oj < 4; oj++){
        float lo0,hi0, lo1,hi1, lo2,hi2, lo3,hi3;
        UNPACK2(lo0, hi0, acc[ 0+oj]);
        UNPACK2(lo1, hi1, acc[ 4+oj]);
        UNPACK2(lo2, hi2, acc[ 8+oj]);
        UNPACK2(lo3, hi3, acc[12+oj]);
        float4 vlo = { fmaxf(lo0,0.f), fmaxf(lo1,0.f), fmaxf(lo2,0.f), fmaxf(lo3,0.f) };
        float4 vhi = { fmaxf(hi0,0.f), fmaxf(hi1,0.f), fmaxf(hi2,0.f), fmaxf(hi3,0.f) };
        *(float4*)(act + (o0 + 2*oj    )*128 + m0) = vlo;
        *(float4*)(act + (o0 + 2*oj + 1)*128 + m0) = vhi;
    }
    __syncthreads();   // layer-1 activations ready

    // ===== layer 2 =====
    {
        const u64* tp = (const u64*)(g_t2 + o0);
        u64 t0p = tp[0], t1p = tp[1], t2p = tp[2], t3p = tp[3];
#pragma unroll
        for (int mi = 0; mi < 4; mi++){
            acc[mi*4+0]=t0p; acc[mi*4+1]=t1p; acc[mi*4+2]=t2p; acc[mi*4+3]=t3p;
        }
        const float* W = g_W2t + o0;
#pragma unroll 8
        for (int c = 0; c < 64; c++){
            float4 a = *(const float4*)(act + c*128 + m0);
            u64 ax, ay, az, aw;
            PACK2(ax, a.x); PACK2(ay, a.y); PACK2(az, a.z); PACK2(aw, a.w);
            ulonglong2 b01 = __ldg((const ulonglong2*)(W + c*64));
            ulonglong2 b23 = __ldg((const ulonglong2*)(W + c*64 + 4));
            FMA2(acc[ 0], ax, b01.x, acc[ 0]); FMA2(acc[ 1], ax, b01.y, acc[ 1]);
            FMA2(acc[ 2], ax, b23.x, acc[ 2]); FMA2(acc[ 3], ax, b23.y, acc[ 3]);
            FMA2(acc[ 4], ay, b01.x, acc[ 4]); FMA2(acc[ 5], ay, b01.y, acc[ 5]);
            FMA2(acc[ 6], ay, b23.x, acc[ 6]); FMA2(acc[ 7], ay, b23.y, acc[ 7]);
            FMA2(acc[ 8], az, b01.x, acc[ 8]); FMA2(acc[ 9], az, b01.y, acc[ 9]);
            FMA2(acc[10], az, b23.x, acc[10]); FMA2(acc[11], az, b23.y, acc[11]);
            FMA2(acc[12], aw, b01.x, acc[12]); FMA2(acc[13], aw, b01.y, acc[13]);
            FMA2(acc[14], aw, b23.x, acc[14]); FMA2(acc[15], aw, b23.y, acc[15]);
        }
    }

    // ===== epilogue: relu + masked per-point partials =====
    {
        const float vf0 = validf[m0+0], vf1 = validf[m0+1];
        const float vf2 = validf[m0+2], vf3 = validf[m0+3];
#pragma unroll
        for (int oj = 0; oj < 4; oj++){
            float lo0,hi0, lo1,hi1, lo2,hi2, lo3,hi3;
            UNPACK2(lo0, hi0, acc[ 0+oj]);
            UNPACK2(lo1, hi1, acc[ 4+oj]);
            UNPACK2(lo2, hi2, acc[ 8+oj]);
            UNPACK2(lo3, hi3, acc[12+oj]);
            float slo = fmaxf(lo0,0.f)*vf0 + fmaxf(lo1,0.f)*vf1
                      + fmaxf(lo2,0.f)*vf2 + fmaxf(lo3,0.f)*vf3;
            float shi = fmaxf(hi0,0.f)*vf0 + fmaxf(hi1,0.f)*vf1
                      + fmaxf(hi2,0.f)*vf2 + fmaxf(hi3,0.f)*vf3;
            part[mt*64 + o0 + 2*oj    ] = slo;
            part[mt*64 + o0 + 2*oj + 1] = shi;
        }
    }
    __syncthreads();

    // ===== final: deterministic 4-way sum + mean + shortcut + relu =====
#pragma unroll
    for (int s = 0; s < 2; s++){
        const int idx = tid + s*256;
        const int o   = idx >> 3;
        const int pl  = idx & 7;
        const int pt  = pt0 + pl;
        const int p   = pt & (NP-1);
        float sum = part[(pl*4+0)*64 + o] + part[(pl*4+1)*64 + o]
                  + part[(pl*4+2)*64 + o] + part[(pl*4+3)*64 + o];
        float denom = fmaxf(vcnt[pl], 1e-8f);
        float res = fmaxf(sum/denom + g_SC[(size_t)pt*64 + o], 0.f);
        out[((size_t)n*64 + o)*NP + p] = res;
    }
}

// ---------------- launch ----------------
extern "C" void kernel_launch(void* const* d_in, const int* in_sizes, int n_in,
                              void* d_out, int out_size)
{
    const float* feats = (const float*)d_in[0];
    const unsigned char* mask = (const unsigned char*)d_in[1];
    const float* W0 = (const float*)d_in[2];
    const float* W1 = (const float*)d_in[3];
    const float* W2 = (const float*)d_in[4];
    const float* Ws = (const float*)d_in[5];

    fold_kernel<<<16, 256>>>(W0, W1, W2, Ws,
        (const float*)d_in[6],  (const float*)d_in[7],  (const float*)d_in[8],  (const float*)d_in[9],
        (const float*)d_in[10], (const float*)d_in[11], (const float*)d_in[12], (const float*)d_in[13],
        (const float*)d_in[14], (const float*)d_in[15], (const float*)d_in[16], (const float*)d_in[17],
        (const float*)d_in[18], (const float*)d_in[19], (const float*)d_in[20], (const float*)d_in[21]);

    prep_kernel<<<NB*NP/4, 256>>>(feats, mask);
    knn_kernel<<<NB*128, 256>>>(feats, mask);
    edge_kernel<<<NB*NP/8, 256>>>((float*)d_out);
}

// round 6
// speedup vs baseline: 3.5180x; 1.0681x over previous
#include <cuda_runtime.h>

#define NB 64
#define NP 1024
#define CF 16
#define KK 16
#define BN_EPS 1e-5f

typedef unsigned long long u64;

#define FMA2(d, a, b, c) \
    asm("fma.rn.f32x2 %0, %1, %2, %3;" : "=l"(d) : "l"(a), "l"(b), "l"(c))
#define PACK2(d, x) \
    asm("mov.b64 %0, {%1, %1};" : "=l"(d) : "f"(x))
#define UNPACK2(lo, hi, v) \
    asm("mov.b64 {%0, %1}, %2;" : "=f"(lo), "=f"(hi) : "l"(v))

// ---------------- static scratch (no allocations allowed) ----------------
__device__ float g_C [NB*NP*64];   // per-point center projection (BN-folded)
__device__ float g_Y [NB*NP*64];   // per-point neighbor projection (scaled)
__device__ float g_SC[NB*NP*64];   // shortcut (BN-folded, mask-zeroed)
__device__ int   g_idx[NB*NP*KK];  // knn indices
__device__ int   g_valid[NB];
__device__ float g_W1t[64*64];     // W1 (BN-scaled), TRANSPOSED: [c][o]
__device__ float g_W2t[64*64];     // W2 (BN-scaled), TRANSPOSED: [c][o]
__device__ float g_W0at[CF*64];    // (W0a+W0b)*s0, transposed [c][o]
__device__ float g_W0bt[CF*64];    // W0b*s0, transposed [c][o]
__device__ float g_Wst [CF*64];    // Ws*ss, transposed [c][o]
__device__ float g_t0[64], g_t1[64], g_t2[64], g_ts[64];

// ---------------- fold BN into weights / biases ----------------
__global__ void fold_kernel(const float* __restrict__ W0, const float* __restrict__ W1,
    const float* __restrict__ W2, const float* __restrict__ Ws,
    const float* g0,const float* b0,const float* m0,const float* v0,
    const float* g1,const float* b1,const float* m1,const float* v1,
    const float* g2,const float* b2,const float* m2,const float* v2,
    const float* gs,const float* bs,const float* ms,const float* vs)
{
    int t = blockIdx.x*blockDim.x + threadIdx.x;
    if (t < 64){
        float s0 = g0[t]*rsqrtf(v0[t]+BN_EPS); g_t0[t]=b0[t]-m0[t]*s0;
        float s1 = g1[t]*rsqrtf(v1[t]+BN_EPS); g_t1[t]=b1[t]-m1[t]*s1;
        float s2 = g2[t]*rsqrtf(v2[t]+BN_EPS); g_t2[t]=b2[t]-m2[t]*s2;
        float ss = gs[t]*rsqrtf(vs[t]+BN_EPS); g_ts[t]=bs[t]-ms[t]*ss;
    }
    if (t < 1024){
        int o = t >> 4;
        int c = t & 15;
        float s0 = g0[o]*rsqrtf(v0[o]+BN_EPS);
        float ss = gs[o]*rsqrtf(vs[o]+BN_EPS);
        float wa = W0[o*32 + c];
        float wb = W0[o*32 + 16 + c];
        g_W0at[c*64 + o] = (wa + wb)*s0;
        g_W0bt[c*64 + o] = wb*s0;
        g_Wst [c*64 + o] = Ws[o*16 + c]*ss;
    }
    if (t < 4096){
        int oo = t >> 6;
        int cc = t & 63;
        g_W1t[cc*64 + oo] = W1[t]*(g1[oo]*rsqrtf(v1[oo]+BN_EPS));
        g_W2t[cc*64 + oo] = W2[t]*(g2[oo]*rsqrtf(v2[oo]+BN_EPS));
    }
}

// ---------------- per-point projections: C, Y, shortcut (coalesced) ----------------
__global__ void prep_kernel(const float* __restrict__ feats,
                            const unsigned char* __restrict__ mask)
{
    const int lp = threadIdx.x >> 6;
    const int o  = threadIdx.x & 63;
    const int pt = blockIdx.x*4 + lp;
    __shared__ float sx[4][CF];
    if (o < CF) sx[lp][o] = feats[pt*(2+CF) + 2 + o];
    __syncthreads();
    float a = 0.f, yb = 0.f, sc = 0.f;
#pragma unroll
    for (int c = 0; c < CF; c++){
        float x = sx[lp][c];
        a  = fmaf(x, g_W0at[c*64 + o], a);
        yb = fmaf(x, g_W0bt[c*64 + o], yb);
        sc = fmaf(x, g_Wst [c*64 + o], sc);
    }
    g_C[pt*64 + o] = a + g_t0[o];
    g_Y[pt*64 + o] = yb;
    float scv = sc + g_ts[o];
    if (mask[pt]) scv = 0.f;
    g_SC[pt*64 + o] = scv;
}

// ---------------- KNN: warp-per-point, branch-free bitonic ----------------
__global__ void __launch_bounds__(256)
knn_kernel(const float* __restrict__ feats,
           const unsigned char* __restrict__ mask)
{
    const int n    = blockIdx.x >> 7;
    const int bloc = blockIdx.x & 127;
    const int warp = threadIdx.x >> 5;
    const int lane = threadIdx.x & 31;
    const int p    = bloc*8 + warp;

    __shared__ float px[NP], py[NP], rr[NP];
    __shared__ unsigned int heads[8][512];
    __shared__ int scnt;

    if (threadIdx.x == 0) scnt = 0;
    int mcnt = 0;
    for (int i = threadIdx.x; i < NP; i += 256){
        float x = feats[(n*NP + i)*(2+CF) + 0];
        float y = feats[(n*NP + i)*(2+CF) + 1];
        px[i] = x; py[i] = y; rr[i] = x*x + y*y;
        if (bloc == 0 && mask[n*NP + i]) mcnt++;
    }
    __syncthreads();
    if (bloc == 0 && mcnt) atomicAdd(&scnt, mcnt);

    const float xp = px[p], yp = py[p], rp = rr[p];
    const float nx = -2.f*xp, ny = -2.f*yp;

    unsigned int key[32];
#pragma unroll
    for (int i = 0; i < 32; i++){
        int q = i*32 + lane;
        float d = fmaxf(fmaf(nx, px[q], fmaf(ny, py[q], rp + rr[q])), 0.f);
        unsigned int kb = (__float_as_uint(d) & 0xFFFFFC00u) | (unsigned int)q;
        key[i] = (q == p) ? 0xFFFFFFFFu : kb;
    }

#pragma unroll
    for (int kk = 2; kk <= 32; kk <<= 1){
#pragma unroll
        for (int j = kk >> 1; j > 0; j >>= 1){
#pragma unroll
            for (int i = 0; i < 32; i++){
                int l = i ^ j;
                if (l > i){
                    unsigned int a = key[i], b = key[l];
                    unsigned int lo = a < b ? a : b;
                    unsigned int hi = a < b ? b : a;
                    if ((i & kk) == 0){ key[i] = lo; key[l] = hi; }
                    else              { key[i] = hi; key[l] = lo; }
                }
            }
        }
    }

#pragma unroll
    for (int j = 0; j < 16; j++) heads[warp][j*32 + lane] = key[j];

    int ptr = 0;
    unsigned int sel = 0;
#pragma unroll 1
    for (int r = 0; r < KK; r++){
        unsigned int h = (ptr < 16) ? heads[warp][ptr*32 + lane] : 0xFFFFFFFFu;
        unsigned int w = h;
#pragma unroll
        for (int d = 16; d; d >>= 1){
            unsigned int o = __shfl_xor_sync(0xFFFFFFFFu, w, d);
            w = (o < w) ? o : w;
        }
        if (h == w) ptr++;
        if (lane == r) sel = w;
    }
    if (lane < KK) g_idx[(n*NP + p)*KK + lane] = (int)(sel & 1023u);

    if (bloc == 0){
        __syncthreads();
        if (threadIdx.x == 0) g_valid[n] = NP - scnt;
    }
}

// ---------------- edge kernel v4: warp-local 32Mx32N sub-tiles ----------------
// Within a warp: mt = lane>>2 (8 x 4M, 4-way act broadcast -> 1 wf/LDS.128),
// ot = lane&3 (4 x 8N, weight LDG.128 within one 128B line -> 1 wf each).
// Warps tile 4M-groups x 2N-groups over the 128x64 block tile.
__global__ void __launch_bounds__(256)
edge_kernel(float* __restrict__ out)
{
    const int tid = threadIdx.x;
    const int pt0 = blockIdx.x * 8;
    const int n   = pt0 >> 10;

    __shared__ float act[64*128];
    __shared__ float part[32*64];
    __shared__ float validf[128];
    __shared__ float vcnt[8];

    const int valid = g_valid[n];

    // ---- phase 0: layer-0 activations into act[c][m] ----
    {
        const int m  = tid >> 1;
        const int h  = tid & 1;
        const int pt = pt0 + (m >> 4);
        const int q  = g_idx[pt*KK + (m & 15)];
        if (h == 0) validf[m] = (q < valid) ? 1.f : 0.f;
        const float4* Yq = (const float4*)(g_Y + ((size_t)n*NP + q)*64) + h*8;
        const float4* Cp = (const float4*)(g_C + (size_t)pt*64) + h*8;
#pragma unroll
        for (int j = 0; j < 8; j++){
            float4 y = Yq[j];
            float4 c = Cp[j];
            int cc = h*32 + j*4;
            act[(cc+0)*128 + m] = fmaxf(c.x - y.x, 0.f);
            act[(cc+1)*128 + m] = fmaxf(c.y - y.y, 0.f);
            act[(cc+2)*128 + m] = fmaxf(c.z - y.z, 0.f);
            act[(cc+3)*128 + m] = fmaxf(c.w - y.w, 0.f);
        }
    }
    __syncthreads();

    if (tid < 8){
        float s = 0.f;
#pragma unroll
        for (int j = 0; j < 16; j++) s += validf[tid*16 + j];
        vcnt[tid] = s;
    }

    // ---- warp-local tiling ----
    const int lane  = tid & 31;
    const int warp  = tid >> 5;
    const int mwarp = warp & 3;          // 4 M-groups of 32
    const int nwarp = warp >> 2;         // 2 N-groups of 32
    const int m0    = mwarp*32 + (lane >> 2)*4;   // 4 M rows
    const int o0    = nwarp*32 + (lane & 3)*8;    // 8 N cols
    const int mtg   = m0 >> 2;           // global M-tile index 0..31

    // acc[mi*4 + oj] = packed outputs (o0+2oj, o0+2oj+1) for M-row m0+mi
    u64 acc[16];

    // ===== layer 1 =====
    {
        const u64* tp = (const u64*)(g_t1 + o0);
        u64 t0p = tp[0], t1p = tp[1], t2p = tp[2], t3p = tp[3];
#pragma unroll
        for (int mi = 0; mi < 4; mi++){
            acc[mi*4+0]=t0p; acc[mi*4+1]=t1p; acc[mi*4+2]=t2p; acc[mi*4+3]=t3p;
        }
        const float* W = g_W1t + o0;
#pragma unroll 8
        for (int c = 0; c < 64; c++){
            float4 a = *(const float4*)(act + c*128 + m0);
            u64 ax, ay, az, aw;
            PACK2(ax, a.x); PACK2(ay, a.y); PACK2(az, a.z); PACK2(aw, a.w);
            ulonglong2 b01 = __ldg((const ulonglong2*)(W + c*64));
            ulonglong2 b23 = __ldg((const ulonglong2*)(W + c*64 + 4));
            FMA2(acc[ 0], ax, b01.x, acc[ 0]); FMA2(acc[ 1], ax, b01.y, acc[ 1]);
            FMA2(acc[ 2], ax, b23.x, acc[ 2]); FMA2(acc[ 3], ax, b23.y, acc[ 3]);
            FMA2(acc[ 4], ay, b01.x, acc[ 4]); FMA2(acc[ 5], ay, b01.y, acc[ 5]);
            FMA2(acc[ 6], ay, b23.x, acc[ 6]); FMA2(acc[ 7], ay, b23.y, acc[ 7]);
            FMA2(acc[ 8], az, b01.x, acc[ 8]); FMA2(acc[ 9], az, b01.y, acc[ 9]);
            FMA2(acc[10], az, b23.x, acc[10]); FMA2(acc[11], az, b23.y, acc[11]);
            FMA2(acc[12], aw, b01.x, acc[12]); FMA2(acc[13], aw, b01.y, acc[13]);
            FMA2(acc[14], aw, b23.x, acc[14]); FMA2(acc[15], aw, b23.y, acc[15]);
        }
    }
    __syncthreads();   // all reads of act complete

    // relu + transposed writeback via STS.128
#pragma unroll
    for (int oj = 0; oj < 4; oj++){
        float lo0,hi0, lo1,hi1, lo2,hi2, lo3,hi3;
        UNPACK2(lo0, hi0, acc[ 0+oj]);
        UNPACK2(lo1, hi1, acc[ 4+oj]);
        UNPACK2(lo2, hi2, acc[ 8+oj]);
        UNPACK2(lo3, hi3, acc[12+oj]);
        float4 vlo = { fmaxf(lo0,0.f), fmaxf(lo1,0.f), fmaxf(lo2,0.f), fmaxf(lo3,0.f) };
        float4 vhi = { fmaxf(hi0,0.f), fmaxf(hi1,0.f), fmaxf(hi2,0.f), fmaxf(hi3,0.f) };
        *(float4*)(act + (o0 + 2*oj    )*128 + m0) = vlo;
        *(float4*)(act + (o0 + 2*oj + 1)*128 + m0) = vhi;
    }
    __syncthreads();   // layer-1 activations ready

    // ===== layer 2 =====
    {
        const u64* tp = (const u64*)(g_t2 + o0);
        u64 t0p = tp[0], t1p = tp[1], t2p = tp[2], t3p = tp[3];
#pragma unroll
        for (int mi = 0; mi < 4; mi++){
            acc[mi*4+0]=t0p; acc[mi*4+1]=t1p; acc[mi*4+2]=t2p; acc[mi*4+3]=t3p;
        }
        const float* W = g_W2t + o0;
#pragma unroll 8
        for (int c = 0; c < 64; c++){
            float4 a = *(const float4*)(act + c*128 + m0);
            u64 ax, ay, az, aw;
            PACK2(ax, a.x); PACK2(ay, a.y); PACK2(az, a.z); PACK2(aw, a.w);
            ulonglong2 b01 = __ldg((const ulonglong2*)(W + c*64));
            ulonglong2 b23 = __ldg((const ulonglong2*)(W + c*64 + 4));
            FMA2(acc[ 0], ax, b01.x, acc[ 0]); FMA2(acc[ 1], ax, b01.y, acc[ 1]);
            FMA2(acc[ 2], ax, b23.x, acc[ 2]); FMA2(acc[ 3], ax, b23.y, acc[ 3]);
            FMA2(acc[ 4], ay, b01.x, acc[ 4]); FMA2(acc[ 5], ay, b01.y, acc[ 5]);
            FMA2(acc[ 6], ay, b23.x, acc[ 6]); FMA2(acc[ 7], ay, b23.y, acc[ 7]);
            FMA2(acc[ 8], az, b01.x, acc[ 8]); FMA2(acc[ 9], az, b01.y, acc[ 9]);
            FMA2(acc[10], az, b23.x, acc[10]); FMA2(acc[11], az, b23.y, acc[11]);
            FMA2(acc[12], aw, b01.x, acc[12]); FMA2(acc[13], aw, b01.y, acc[13]);
            FMA2(acc[14], aw, b23.x, acc[14]); FMA2(acc[15], aw, b23.y, acc[15]);
        }
    }

    // ===== epilogue: relu + masked per-point partials =====
    {
        const float vf0 = validf[m0+0], vf1 = validf[m0+1];
        const float vf2 = validf[m0+2], vf3 = validf[m0+3];
#pragma unroll
        for (int oj = 0; oj < 4; oj++){
            float lo0,hi0, lo1,hi1, lo2,hi2, lo3,hi3;
            UNPACK2(lo0, hi0, acc[ 0+oj]);
            UNPACK2(lo1, hi1, acc[ 4+oj]);
            UNPACK2(lo2, hi2, acc[ 8+oj]);
            UNPACK2(lo3, hi3, acc[12+oj]);
            float slo = fmaxf(lo0,0.f)*vf0 + fmaxf(lo1,0.f)*vf1
                      + fmaxf(lo2,0.f)*vf2 + fmaxf(lo3,0.f)*vf3;
            float shi = fmaxf(hi0,0.f)*vf0 + fmaxf(hi1,0.f)*vf1
                      + fmaxf(hi2,0.f)*vf2 + fmaxf(hi3,0.f)*vf3;
            part[mtg*64 + o0 + 2*oj    ] = slo;
            part[mtg*64 + o0 + 2*oj + 1] = shi;
        }
    }
    __syncthreads();

    // ===== final: deterministic 4-way sum + mean + shortcut + relu =====
#pragma unroll
    for (int s = 0; s < 2; s++){
        const int idx = tid + s*256;
        const int o   = idx >> 3;
        const int pl  = idx & 7;
        const int pt  = pt0 + pl;
        const int p   = pt & (NP-1);
        float sum = part[(pl*4+0)*64 + o] + part[(pl*4+1)*64 + o]
                  + part[(pl*4+2)*64 + o] + part[(pl*4+3)*64 + o];
        float denom = fmaxf(vcnt[pl], 1e-8f);
        float res = fmaxf(sum/denom + g_SC[(size_t)pt*64 + o], 0.f);
        out[((size_t)n*64 + o)*NP + p] = res;
    }
}

// ---------------- launch ----------------
extern "C" void kernel_launch(void* const* d_in, const int* in_sizes, int n_in,
                              void* d_out, int out_size)
{
    const float* feats = (const float*)d_in[0];
    const unsigned char* mask = (const unsigned char*)d_in[1];
    const float* W0 = (const float*)d_in[2];
    const float* W1 = (const float*)d_in[3];
    const float* W2 = (const float*)d_in[4];
    const float* Ws = (const float*)d_in[5];

    fold_kernel<<<16, 256>>>(W0, W1, W2, Ws,
        (const float*)d_in[6],  (const float*)d_in[7],  (const float*)d_in[8],  (const float*)d_in[9],
        (const float*)d_in[10], (const float*)d_in[11], (const float*)d_in[12], (const float*)d_in[13],
        (const float*)d_in[14], (const float*)d_in[15], (const float*)d_in[16], (const float*)d_in[17],
        (const float*)d_in[18], (const float*)d_in[19], (const float*)d_in[20], (const float*)d_in[21]);

    prep_kernel<<<NB*NP/4, 256>>>(feats, mask);
    knn_kernel<<<NB*128, 256>>>(feats, mask);
    edge_kernel<<<NB*NP/8, 256>>>((float*)d_out);
}